// round 8
// baseline (speedup 1.0000x reference)
#include <cuda_runtime.h>
#include <cuda_bf16.h>
#include <cstdint>

#define BATCH     8192
#define NCLASSES  8192
#define NGROUPS   512
#define PAD       128            // >= max group size (Poisson(16); huge margin)
#define NWARP     16             // k_main warps per block
#define MAXSLOT   128            // schedule capacity (2x u64 masks)

// smem float-index layout for k_main
#define ROWB      8224           // row1 base: (8224*4)%128==0 (TMA ok), 8224%32==0 (bank shift 0)
#define SMEM_FLOATS 16448        // 8192 row0 | 32 zeros | 8192 row1 | 32 zeros  (65792 B)

// Scratch: __device__ globals only (allocation is forbidden).
__device__ unsigned short g_perm_pad[NGROUPS * PAD];      // per-group columns (stable)
__device__ int            g_cnt[NGROUPS];                 // group sizes
__device__ unsigned short g_sched[NWARP * MAXSLOT * 32];  // [warp][slot][lane] column or sentinel
__device__ int            g_nslots[NWARP];                // used slots per warp

// ---------------------------------------------------------------------------
// K1: build padded, stable per-group column lists + counts.
// 64 blocks x 256 threads; block stages seg to smem, 8 warps own 1 group each.
// ---------------------------------------------------------------------------
__global__ __launch_bounds__(256)
void k_perm(const int* __restrict__ seg) {
    __shared__ int sseg[NCLASSES];
    const int t = threadIdx.x;

    const int4* s4 = (const int4*)seg;
    int4*       d4 = (int4*)sseg;
    #pragma unroll
    for (int k = 0; k < (NCLASSES / 4) / 256; ++k)
        d4[t + k * 256] = s4[t + k * 256];
    __syncthreads();

    const int      lane = t & 31;
    const int      g    = blockIdx.x * 8 + (t >> 5);
    const unsigned lm   = (1u << lane) - 1u;
    unsigned short* dst = g_perm_pad + g * PAD;

    int cnt = 0;
    for (int c0 = 0; c0 < NCLASSES; c0 += 128) {
        const int s0 = sseg[c0 +  0 + lane];
        const int s1 = sseg[c0 + 32 + lane];
        const int s2 = sseg[c0 + 64 + lane];
        const int s3 = sseg[c0 + 96 + lane];
        const unsigned m0 = __ballot_sync(0xffffffffu, s0 == g);
        const unsigned m1 = __ballot_sync(0xffffffffu, s1 == g);
        const unsigned m2 = __ballot_sync(0xffffffffu, s2 == g);
        const unsigned m3 = __ballot_sync(0xffffffffu, s3 == g);
        const int p0 = __popc(m0), p1 = __popc(m1), p2 = __popc(m2), p3 = __popc(m3);
        if (s0 == g) dst[cnt                + __popc(m0 & lm)] = (unsigned short)(c0 +  0 + lane);
        if (s1 == g) dst[cnt + p0           + __popc(m1 & lm)] = (unsigned short)(c0 + 32 + lane);
        if (s2 == g) dst[cnt + p0 + p1      + __popc(m2 & lm)] = (unsigned short)(c0 + 64 + lane);
        if (s3 == g) dst[cnt + p0 + p1 + p2 + __popc(m3 & lm)] = (unsigned short)(c0 + 96 + lane);
        cnt += p0 + p1 + p2 + p3;
    }
    if (lane == 0) g_cnt[g] = cnt;
}

// ---------------------------------------------------------------------------
// K2: build conflict-free gather schedule. One block, 16 warps; warp w solves
// the (lane x bank) edge coloring for k_main warp w (groups 32w..32w+31).
// Deterministic greedy: per column, same-bank lanes arbitrate via match_any
// (lowest lane wins), slot = first bit free in lane-mask AND bank-mask.
// Result: each slot's 32 columns hit 32 distinct smem banks -> 1-phase LDS.
// ---------------------------------------------------------------------------
__global__ __launch_bounds__(512)
void k_sched() {
    __shared__ unsigned long long bu[NWARP][32][2];   // per-warp per-bank slot masks
    const int t = threadIdx.x, w = t >> 5, lane = t & 31;

    // Init schedule to per-lane sentinels 8192+lane (points at zero pad, bank==lane).
    unsigned* p = (unsigned*)g_sched;
    for (int i = t; i < NWARP * MAXSLOT * 16; i += 512) {
        const int lp = (i & 15) * 2;
        p[i] = (unsigned)(8192 + lp) | ((unsigned)(8193 + lp) << 16);
    }
    bu[w][lane][0] = 0ull;
    bu[w][lane][1] = 0ull;
    __syncthreads();

    const int g    = 32 * w + lane;
    const int cnt  = g_cnt[g];
    const int nmax = __reduce_max_sync(0xffffffffu, cnt);

    unsigned long long lu0 = 0ull, lu1 = 0ull;        // this lane's used slots
    int maxslot = -1;

    for (int k = 0; k < nmax; ++k) {
        bool pend = (k < cnt);
        const unsigned c = pend ? (unsigned)g_perm_pad[g * PAD + k] : 0u;
        const int b = (int)(c & 31u);
        while (__any_sync(0xffffffffu, pend)) {
            int s = 0;
            if (pend) {
                const unsigned long long m0 = ~(lu0 | bu[w][b][0]);
                const unsigned long long m1 = ~(lu1 | bu[w][b][1]);
                s = m0 ? (__ffsll(m0) - 1) : (64 + __ffsll(m1) - 1);
            }
            const unsigned key = pend ? (unsigned)b : (256u + (unsigned)lane);
            const unsigned grp = __match_any_sync(0xffffffffu, key);
            if (pend && (int)(__ffs(grp) - 1) == lane) {   // bank leader places
                if (s < 64) { lu0 |= 1ull << s;        bu[w][b][0] |= 1ull << s; }
                else        { lu1 |= 1ull << (s - 64); bu[w][b][1] |= 1ull << (s - 64); }
                g_sched[(w * MAXSLOT + s) * 32 + lane] = (unsigned short)c;
                if (s > maxslot) maxslot = s;
                pend = false;
            }
            __syncwarp();
        }
    }
    const int n = __reduce_max_sync(0xffffffffu, maxslot + 1);
    if (lane == 0) g_nslots[w] = n;
}

// ---------------------------------------------------------------------------
// K3: hot kernel. Two 32KB rows staged by cp.async.bulk (TMA path). Gather is
// bank-conflict-free by construction: per warp, slot s reads 32 distinct-bank
// columns (sentinels hit per-lane zero pads). Uniform per-warp trip count,
// coalesced schedule reads, coalesced output.
// ---------------------------------------------------------------------------
__global__ __launch_bounds__(512, 3)
void k_main(const float* __restrict__ x, float* __restrict__ out) {
    extern __shared__ float srow[];                  // [0,8192) row0, [8224,16416) row1
    __shared__ __align__(8) unsigned long long mbar;

    const int t = threadIdx.x;
    const int w = t >> 5, lane = t & 31;
    const size_t row0 = (size_t)blockIdx.x * 2;

    unsigned mbar_a, srow_a;
    asm("{ .reg .u64 a; cvta.to.shared.u64 a, %1; cvt.u32.u64 %0, a; }"
        : "=r"(mbar_a) : "l"(&mbar));
    asm("{ .reg .u64 a; cvta.to.shared.u64 a, %1; cvt.u32.u64 %0, a; }"
        : "=r"(srow_a) : "l"(srow));

    if (t < 32) {                                    // per-lane sentinel zero pads
        srow[8192 + t]        = 0.f;
        srow[ROWB + 8192 + t] = 0.f;
    }
    if (t == 0)
        asm volatile("mbarrier.init.shared.b64 [%0], 1;" :: "r"(mbar_a) : "memory");
    __syncthreads();

    if (t == 0) {
        asm volatile("mbarrier.arrive.expect_tx.shared.b64 _, [%0], %1;"
                     :: "r"(mbar_a), "r"(2 * NCLASSES * 4) : "memory");
        const float* src = x + row0 * NCLASSES;
        asm volatile("cp.async.bulk.shared::cta.global.mbarrier::complete_tx::bytes [%0], [%1], %2, [%3];"
                     :: "r"(srow_a), "l"(src), "r"(NCLASSES * 4), "r"(mbar_a) : "memory");
        asm volatile("cp.async.bulk.shared::cta.global.mbarrier::complete_tx::bytes [%0], [%1], %2, [%3];"
                     :: "r"(srow_a + ROWB * 4), "l"(src + NCLASSES), "r"(NCLASSES * 4), "r"(mbar_a) : "memory");
    }

    // Overlap with the copy: per-warp slot count + schedule base.
    const int n = g_nslots[w];                        // uniform within warp
    const unsigned short* __restrict__ sp = g_sched + w * (MAXSLOT * 32) + lane;

    {   // wait for both bulk copies (acquire orders TMA smem writes before LDS)
        unsigned done = 0;
        while (!done) {
            asm volatile(
                "{\n\t.reg .pred P;\n\t"
                "mbarrier.try_wait.parity.acquire.cta.shared::cta.b64 P, [%1], 0, 0x989680;\n\t"
                "selp.b32 %0, 1, 0, P;\n\t}"
                : "=r"(done) : "r"(mbar_a) : "memory");
        }
    }

    float a0 = 0.f, a1 = 0.f, a2 = 0.f, a3 = 0.f;     // row0 chains
    float b0 = 0.f, b1 = 0.f, b2 = 0.f, b3 = 0.f;     // row1 chains
    int s = 0;
    for (; s + 4 <= n; s += 4) {
        const int i0 = sp[(s + 0) * 32];
        const int i1 = sp[(s + 1) * 32];
        const int i2 = sp[(s + 2) * 32];
        const int i3 = sp[(s + 3) * 32];
        a0 += srow[i0]; b0 += srow[ROWB + i0];
        a1 += srow[i1]; b1 += srow[ROWB + i1];
        a2 += srow[i2]; b2 += srow[ROWB + i2];
        a3 += srow[i3]; b3 += srow[ROWB + i3];
    }
    for (; s < n; ++s) {
        const int i0 = sp[s * 32];
        a0 += srow[i0]; b0 += srow[ROWB + i0];
    }

    const int g = t;                                  // group = thread (lane of warp w)
    out[row0 * NGROUPS + g]       = (a0 + a1) + (a2 + a3);
    out[(row0 + 1) * NGROUPS + g] = (b0 + b1) + (b2 + b3);
}

// ---------------------------------------------------------------------------
// Launch
// ---------------------------------------------------------------------------
extern "C" void kernel_launch(void* const* d_in, const int* in_sizes, int n_in,
                              void* d_out, int out_size) {
    const float* x   = (const float*)d_in[0];
    const int*   seg = (const int*)d_in[1];
    float*       out = (float*)d_out;

    const int smem_main = SMEM_FLOATS * (int)sizeof(float);   // 65792 B
    cudaFuncSetAttribute(k_main, cudaFuncAttributeMaxDynamicSharedMemorySize,
                         smem_main);

    k_perm<<<NGROUPS / 8, 256>>>(seg);
    k_sched<<<1, 512>>>();
    k_main<<<BATCH / 2, 512, smem_main>>>(x, out);
}